// round 7
// baseline (speedup 1.0000x reference)
#include <cuda_runtime.h>
#include <cstdint>

#define LQ 64
#define DQ 128
#define EPSQ 1e-6f
#define MAXB 2048

// Precomputed: Vp = relu(W1)^T W2, Vn = min(W1,0)^T W2, Vb = 8*b2
__device__ __align__(16) float g_Vp[DQ];
__device__ __align__(16) float g_Vn[DQ];
__device__ __align__(16) float g_Vb[DQ];
__device__ int   g_b1_zero;
// Per-(side,b,l) signed feature sums, row index r = (side*B + b)*LQ + l
__device__ float2 g_S[2 * MAXB * LQ];
// Raw features for the (never-taken) general-b1 path
__device__ float g_feats[2u * MAXB * LQ * 8u];

// ---------------------------------------------------------------------------
__global__ __launch_bounds__(1024)
void prep_kernel(const float* __restrict__ W1,
                 const float* __restrict__ b1,
                 const float* __restrict__ W2,
                 const float* __restrict__ b2) {
    __shared__ float rvp[8][DQ];
    __shared__ float rvn[8][DQ];
    __shared__ int nz;
    const int t  = threadIdx.x;
    const int e  = t & 127;
    const int dg = t >> 7;

    float vp = 0.f, vn = 0.f;
    #pragma unroll
    for (int k = 0; k < 16; ++k) {
        int d = dg * 16 + k;
        float w  = __ldg(&W1[d]);
        float w2 = __ldg(&W2[d * DQ + e]);
        vp = fmaf(fmaxf(w, 0.f), w2, vp);
        vn = fmaf(fminf(w, 0.f), w2, vn);
    }
    rvp[dg][e] = vp;
    rvn[dg][e] = vn;

    if (t == 0) nz = 0;
    __syncthreads();
    if (t < DQ && b1[t] != 0.f) atomicAdd(&nz, 1);
    __syncthreads();

    if (t < DQ) {
        float sp = 0.f, sn = 0.f;
        #pragma unroll
        for (int g = 0; g < 8; ++g) { sp += rvp[g][t]; sn += rvn[g][t]; }
        g_Vp[t] = sp;
        g_Vn[t] = sn;
        g_Vb[t] = 8.f * b2[t];
    }
    if (t == 0) g_b1_zero = (nz == 0) ? 1 : 0;
}

// ---------------------------------------------------------------------------
// Feature kernel: one block per sample, bitmask sparse group stats (as R5),
// ends by writing (Sp, Sn) per position to global scratch. No output stores.
// ---------------------------------------------------------------------------
__global__ __launch_bounds__(256)
void feat_kernel(const int*   __restrict__ src_ids,
                 const int*   __restrict__ dst_ids,
                 const int*   __restrict__ src_nid,
                 const int*   __restrict__ dst_nid,
                 const float* __restrict__ itimes,
                 const float* __restrict__ src_t,
                 const float* __restrict__ dst_t,
                 int B) {
    __shared__ int   s_ids[2][LQ];
    __shared__ float s_t[2][LQ];
    __shared__ float s_avg[2][LQ];
    __shared__ float s_rec[2][LQ];

    const int b   = blockIdx.x;
    const int tid = threadIdx.x;

    if (tid < 128) {
        int sd = tid >> 6, p = tid & 63;
        const int*   ids = sd ? dst_ids : src_ids;
        const float* ts  = sd ? dst_t   : src_t;
        s_ids[sd][p] = ids[b * LQ + p];
        s_t[sd][p]   = ts[b * LQ + p];
    }
    __syncthreads();

    const int fast = g_b1_zero;

    const int half = tid & 1;
    const int pos  = tid >> 1;     // 0..127
    const int side = pos >> 6;     // warp-uniform
    const int i    = pos & 63;
    const int os   = side ^ 1;

    const int   myid = s_ids[side][i];
    const float myt  = s_t[side][i];

    // ---- mask build: j = 2k + half ----
    unsigned loA = 0, hiA = 0, loX = 0, hiX = 0;
    #pragma unroll
    for (int k = 0; k < 16; ++k) {
        int j = (k << 1) | half;
        if (s_ids[side][j] == myid) loA |= (1u << (2 * k));
        if (s_ids[os][j]   == myid) loX |= (1u << (2 * k));
    }
    #pragma unroll
    for (int k = 16; k < 32; ++k) {
        int j = (k << 1) | half;
        if (s_ids[side][j] == myid) hiA |= (1u << (2 * k - 32));
        if (s_ids[os][j]   == myid) hiX |= (1u << (2 * k - 32));
    }
    unsigned long long m_own = (((unsigned long long)hiA << 32) | loA) << half;
    unsigned long long m_oth = (((unsigned long long)hiX << 32) | loX) << half;
    m_own |= __shfl_xor_sync(0xFFFFFFFFu, m_own, 1);
    m_oth |= __shfl_xor_sync(0xFFFFFFFFu, m_oth, 1);

    const int n     = __popcll(m_own);
    const int split = n >> 1;

    // ---- sparse group stats: half0 -> extrema, half1 -> t_split ----
    float tmax = -3.402823466e38f, tmin = 3.402823466e38f, ts = 0.f;
    if (!half) {
        unsigned long long m = m_own;
        while (m) {
            int j = __ffsll((long long)m) - 1;
            m &= m - 1;
            float tj = s_t[side][j];
            tmax = fmaxf(tmax, tj);
            tmin = fminf(tmin, tj);
        }
    } else if (n >= 4) {
        unsigned long long mc = m_own;
        while (mc) {
            int j = __ffsll((long long)mc) - 1;
            mc &= mc - 1;
            float tj = s_t[side][j];
            int r = 0;
            unsigned long long mi = m_own;
            while (mi) {
                int q = __ffsll((long long)mi) - 1;
                mi &= mi - 1;
                float tq = s_t[side][q];
                r += (tq < tj) || (tq == tj && q < j);
            }
            if (r == split) ts = tj;
        }
    }
    ts = __shfl_xor_sync(0xFFFFFFFFu, ts, 1) + ts;

    if (!half) {
        float nf  = (float)n;
        float avg = (n > 1) ? (tmax - tmin) / (nf - 1.f) : 0.f;
        float den = fmaxf(nf - (float)split - 1.f, 1.f);
        float rec = (n >= 4) ? (tmax - ts) / den : 0.f;
        if (myid == 0) { avg = 0.f; rec = 0.f; }
        s_avg[side][i] = avg;
        s_rec[side][i] = rec;
    }
    __syncthreads();

    // ---- features: O(1) cross lookups -> write (Sp, Sn) to scratch ----
    if (!half) {
        float cur_t      = itimes[b];
        int   other_node = side ? src_nid[b] : dst_nid[b];

        int co = __popcll(m_oth);
        float lt = 0.f, iat_o = 0.f, riat_o = 0.f;
        if (m_oth) {
            int jf = __ffsll((long long)m_oth) - 1;
            int jl = 63 - __clzll((long long)m_oth);
            lt     = s_t[os][jl];
            iat_o  = s_avg[os][jf];
            riat_o = s_rec[os][jf];
        }
        float my_avg = s_avg[side][i], my_rec = s_rec[side][i];

        float f0 = (float)n;
        float f1 = (float)co;
        float f2 = (myid == other_node) ? 1.f : 0.f;
        float f3 = (co > 0) ? 1.f : 0.f;
        float f4 = (co > 0) ? f0 / (f1 + EPSQ) : 0.f;
        float rcy_self  = cur_t - myt;
        float rcy_other = cur_t - lt;
        float f5 = (rcy_self > EPSQ) ? rcy_other / (rcy_self + EPSQ) : 0.f;
        float f6 = (iat_o  > EPSQ) ? my_avg / (iat_o  + EPSQ) : 0.f;
        float f7 = (riat_o > EPSQ) ? my_rec / (riat_o + EPSQ) : 0.f;
        if (myid == 0) { f0 = f1 = f2 = f3 = f4 = f5 = f6 = f7 = 0.f; }

        float sp = fmaxf(f0,0.f)+fmaxf(f1,0.f)+fmaxf(f2,0.f)+fmaxf(f3,0.f)
                 + fmaxf(f4,0.f)+fmaxf(f5,0.f)+fmaxf(f6,0.f)+fmaxf(f7,0.f);
        float sn = fminf(f0,0.f)+fminf(f1,0.f)+fminf(f2,0.f)+fminf(f3,0.f)
                 + fminf(f4,0.f)+fminf(f5,0.f)+fminf(f6,0.f)+fminf(f7,0.f);

        int r = (side * B + b) * LQ + i;
        g_S[r] = make_float2(sp, sn);

        if (!fast) {
            float* fp = &g_feats[(size_t)r * 8];
            fp[0]=f0; fp[1]=f1; fp[2]=f2; fp[3]=f3;
            fp[4]=f4; fp[5]=f5; fp[6]=f6; fp[7]=f7;
        }
    }
}

// ---------------------------------------------------------------------------
// Store kernel: pure streaming. Block k writes rows [k*128, k*128+128)
// (row r = (side*B+b)*LQ + l -> out offset r*DQ). No smem, no syncs.
// ---------------------------------------------------------------------------
__global__ __launch_bounds__(256)
void store_kernel(const float* __restrict__ W1,
                  const float* __restrict__ b1,
                  const float* __restrict__ W2,
                  const float* __restrict__ b2,
                  float*       __restrict__ out,
                  int B) {
    const int tid = threadIdx.x;
    const int base = blockIdx.x * 128;          // first row of this block

    if (g_b1_zero) {
        const int e4 = tid & 31;
        const int w  = tid >> 5;                // 0..7
        const float4 vp = ((const float4*)g_Vp)[e4];
        const float4 vn = ((const float4*)g_Vn)[e4];
        const float4 bb = ((const float4*)g_Vb)[e4];
        float4* out4 = (float4*)out;

        #pragma unroll
        for (int it = 0; it < 16; ++it) {
            int r = base + it * 8 + w;          // warp-uniform row
            float2 s = __ldg(&g_S[r]);          // broadcast load
            float4 y;
            y.x = fmaf(s.x, vp.x, fmaf(s.y, vn.x, bb.x));
            y.y = fmaf(s.x, vp.y, fmaf(s.y, vn.y, bb.y));
            y.z = fmaf(s.x, vp.z, fmaf(s.y, vn.z, bb.z));
            y.w = fmaf(s.x, vp.w, fmaf(s.y, vn.w, bb.w));
            __stcs(&out4[(size_t)r * 32 + e4], y);
        }
    } else {
        // ---- general-b1 path (never taken with this dataset's b1 == 0) ----
        __shared__ float sW1[DQ], sb1[DQ];
        if (tid < DQ) { sW1[tid] = W1[tid]; sb1[tid] = b1[tid]; }
        __syncthreads();
        for (int idx = tid; idx < 128 * DQ; idx += 256) {
            int lr = idx >> 7;                  // row within block
            int e  = idx & 127;
            int r  = base + lr;
            const float* fp = &g_feats[(size_t)r * 8];
            float y = 8.f * __ldg(&b2[e]);
            #pragma unroll
            for (int f = 0; f < 8; ++f) {
                float fv  = fp[f];
                float acc = 0.f;
                for (int d = 0; d < DQ; ++d) {
                    float h = fmaxf(fmaf(fv, sW1[d], sb1[d]), 0.f);
                    acc = fmaf(h, __ldg(&W2[d * DQ + e]), acc);
                }
                y += acc;
            }
            out[(size_t)r * DQ + e] = y;
        }
    }
}

// ---------------------------------------------------------------------------
extern "C" void kernel_launch(void* const* d_in, const int* in_sizes, int n_in,
                              void* d_out, int out_size) {
    const int*   src_ids = (const int*)  d_in[0];
    const int*   dst_ids = (const int*)  d_in[1];
    const int*   src_nid = (const int*)  d_in[2];
    const int*   dst_nid = (const int*)  d_in[3];
    const float* itimes  = (const float*)d_in[4];
    const float* src_t   = (const float*)d_in[5];
    const float* dst_t   = (const float*)d_in[6];
    const float* W1      = (const float*)d_in[7];
    const float* b1      = (const float*)d_in[8];
    const float* W2      = (const float*)d_in[9];
    const float* b2      = (const float*)d_in[10];
    float* out = (float*)d_out;
    int B = in_sizes[2];  // src_node_ids count

    prep_kernel<<<1, 1024>>>(W1, b1, W2, b2);
    feat_kernel<<<B, 256>>>(src_ids, dst_ids, src_nid, dst_nid,
                            itimes, src_t, dst_t, B);
    store_kernel<<<B, 256>>>(W1, b1, W2, b2, out, B);   // 2*B*64 rows / 128 = B blocks
}

// round 8
// speedup vs baseline: 1.4107x; 1.4107x over previous
#include <cuda_runtime.h>
#include <cstdint>

#define LQ 64
#define DQ 128
#define EPSQ 1e-6f

// Precomputed: Vp = relu(W1)^T W2, Vn = min(W1,0)^T W2, Vb = 8*b2
__device__ __align__(16) float g_Vp[DQ];
__device__ __align__(16) float g_Vn[DQ];
__device__ __align__(16) float g_Vb[DQ];
__device__ int   g_b1_zero;

// ---------------------------------------------------------------------------
// Prep v3: 4 blocks x 256 threads. Block eb handles e in [32*eb, 32*eb+32).
// Thread (dg = tid>>5, el = tid&31): 16 d's, coalesced 128B W2 row segments.
// ---------------------------------------------------------------------------
__global__ __launch_bounds__(256)
void prep_kernel(const float* __restrict__ W1,
                 const float* __restrict__ b1,
                 const float* __restrict__ W2,
                 const float* __restrict__ b2) {
    __shared__ float rvp[8][32];
    __shared__ float rvn[8][32];
    __shared__ int nz;
    const int t  = threadIdx.x;
    const int el = t & 31;
    const int dg = t >> 5;
    const int e  = blockIdx.x * 32 + el;

    if (t == 0) nz = 0;

    float vp = 0.f, vn = 0.f;
    #pragma unroll
    for (int k = 0; k < 16; ++k) {
        int d = dg * 16 + k;
        float w  = __ldg(&W1[d]);
        float w2 = __ldg(&W2[d * DQ + e]);
        vp = fmaf(fmaxf(w, 0.f), w2, vp);
        vn = fmaf(fminf(w, 0.f), w2, vn);
    }
    rvp[dg][el] = vp;
    rvn[dg][el] = vn;
    __syncthreads();

    if (blockIdx.x == 0 && t < DQ && b1[t] != 0.f) atomicAdd(&nz, 1);

    if (dg == 0) {
        float sp = 0.f, sn = 0.f;
        #pragma unroll
        for (int g = 0; g < 8; ++g) { sp += rvp[g][el]; sn += rvn[g][el]; }
        g_Vp[e] = sp;
        g_Vn[e] = sn;
        g_Vb[e] = 8.f * __ldg(&b2[e]);
    }
    __syncthreads();
    if (blockIdx.x == 0 && t == 0) g_b1_zero = (nz == 0) ? 1 : 0;
}

// ---------------------------------------------------------------------------
// Main: one block per sample. Bitmask sparse group stats (lane pairs), then
// each warp stores its OWN 16 output rows via shfl-broadcast of (Sp,Sn) —
// no block-wide barrier between features and stores.
// ---------------------------------------------------------------------------
__global__ __launch_bounds__(256, 6)
void lpe_main_kernel(const int*   __restrict__ src_ids,
                     const int*   __restrict__ dst_ids,
                     const int*   __restrict__ src_nid,
                     const int*   __restrict__ dst_nid,
                     const float* __restrict__ itimes,
                     const float* __restrict__ src_t,
                     const float* __restrict__ dst_t,
                     const float* __restrict__ W1,
                     const float* __restrict__ b1,
                     const float* __restrict__ W2,
                     const float* __restrict__ b2,
                     float*       __restrict__ out,
                     int B) {
    __shared__ int   s_ids[2][LQ];
    __shared__ float s_t[2][LQ];
    __shared__ float s_avg[2][LQ];
    __shared__ float s_rec[2][LQ];
    __shared__ float s_Vp[DQ], s_Vn[DQ], s_Vb[DQ];
    __shared__ float s_feat[2][LQ][8];   // slow path only

    const int b   = blockIdx.x;
    const int tid = threadIdx.x;

    // early broadcast scalars (overlap with tile load)
    const float cur_t = __ldg(&itimes[b]);
    const int   snid  = __ldg(&src_nid[b]);
    const int   dnid  = __ldg(&dst_nid[b]);

    // ---- load tile ----
    if (tid < 128) {
        int sd = tid >> 6, p = tid & 63;
        const int*   ids = sd ? dst_ids : src_ids;
        const float* ts  = sd ? dst_t   : src_t;
        s_ids[sd][p] = __ldg(&ids[b * LQ + p]);
        s_t[sd][p]   = __ldg(&ts[b * LQ + p]);
    } else {
        int e = tid - 128;
        s_Vp[e] = g_Vp[e];
        s_Vn[e] = g_Vn[e];
        s_Vb[e] = g_Vb[e];
    }
    __syncthreads();

    const int fast = g_b1_zero;

    const int half = tid & 1;
    const int pos  = tid >> 1;     // 0..127
    const int side = pos >> 6;     // warp-uniform
    const int i    = pos & 63;
    const int os   = side ^ 1;

    const int   myid = s_ids[side][i];
    const float myt  = s_t[side][i];

    // ---- mask build: j = 2k + half ----
    unsigned loA = 0, hiA = 0, loX = 0, hiX = 0;
    #pragma unroll
    for (int k = 0; k < 16; ++k) {
        int j = (k << 1) | half;
        if (s_ids[side][j] == myid) loA |= (1u << (2 * k));
        if (s_ids[os][j]   == myid) loX |= (1u << (2 * k));
    }
    #pragma unroll
    for (int k = 16; k < 32; ++k) {
        int j = (k << 1) | half;
        if (s_ids[side][j] == myid) hiA |= (1u << (2 * k - 32));
        if (s_ids[os][j]   == myid) hiX |= (1u << (2 * k - 32));
    }
    unsigned long long m_own = (((unsigned long long)hiA << 32) | loA) << half;
    unsigned long long m_oth = (((unsigned long long)hiX << 32) | loX) << half;
    m_own |= __shfl_xor_sync(0xFFFFFFFFu, m_own, 1);
    m_oth |= __shfl_xor_sync(0xFFFFFFFFu, m_oth, 1);

    const int n     = __popcll(m_own);
    const int split = n >> 1;

    // ---- sparse group stats: half0 -> extrema, half1 -> t_split ----
    float tmax = -3.402823466e38f, tmin = 3.402823466e38f, ts = 0.f;
    if (!half) {
        unsigned long long m = m_own;
        while (m) {
            int j = __ffsll((long long)m) - 1;
            m &= m - 1;
            float tj = s_t[side][j];
            tmax = fmaxf(tmax, tj);
            tmin = fminf(tmin, tj);
        }
    } else if (n >= 4) {
        unsigned long long mc = m_own;
        while (mc) {
            int j = __ffsll((long long)mc) - 1;
            mc &= mc - 1;
            float tj = s_t[side][j];
            int r = 0;
            unsigned long long mi = m_own;
            while (mi) {
                int q = __ffsll((long long)mi) - 1;
                mi &= mi - 1;
                float tq = s_t[side][q];
                r += (tq < tj) || (tq == tj && q < j);
            }
            if (r == split) ts = tj;
        }
    }
    ts = __shfl_xor_sync(0xFFFFFFFFu, ts, 1) + ts;

    float my_avg = 0.f, my_rec = 0.f;
    if (!half) {
        float nf  = (float)n;
        my_avg = (n > 1) ? (tmax - tmin) / (nf - 1.f) : 0.f;
        float den = fmaxf(nf - (float)split - 1.f, 1.f);
        my_rec = (n >= 4) ? (tmax - ts) / den : 0.f;
        if (myid == 0) { my_avg = 0.f; my_rec = 0.f; }
        s_avg[side][i] = my_avg;
        s_rec[side][i] = my_rec;
    }
    __syncthreads();

    // ---- features (half0 lanes): O(1) cross lookups -> (sp, sn) regs ----
    float sp = 0.f, sn = 0.f;
    if (!half) {
        int other_node = side ? snid : dnid;

        int co = __popcll(m_oth);
        float lt = 0.f, iat_o = 0.f, riat_o = 0.f;
        if (m_oth) {
            int jf = __ffsll((long long)m_oth) - 1;
            int jl = 63 - __clzll((long long)m_oth);
            lt     = s_t[os][jl];
            iat_o  = s_avg[os][jf];
            riat_o = s_rec[os][jf];
        }

        float f0 = (float)n;
        float f1 = (float)co;
        float f2 = (myid == other_node) ? 1.f : 0.f;
        float f3 = (co > 0) ? 1.f : 0.f;
        float f4 = (co > 0) ? f0 / (f1 + EPSQ) : 0.f;
        float rcy_self  = cur_t - myt;
        float rcy_other = cur_t - lt;
        float f5 = (rcy_self > EPSQ) ? rcy_other / (rcy_self + EPSQ) : 0.f;
        float f6 = (iat_o  > EPSQ) ? my_avg / (iat_o  + EPSQ) : 0.f;
        float f7 = (riat_o > EPSQ) ? my_rec / (riat_o + EPSQ) : 0.f;
        if (myid == 0) { f0 = f1 = f2 = f3 = f4 = f5 = f6 = f7 = 0.f; }

        sp = fmaxf(f0,0.f)+fmaxf(f1,0.f)+fmaxf(f2,0.f)+fmaxf(f3,0.f)
           + fmaxf(f4,0.f)+fmaxf(f5,0.f)+fmaxf(f6,0.f)+fmaxf(f7,0.f);
        sn = fminf(f0,0.f)+fminf(f1,0.f)+fminf(f2,0.f)+fminf(f3,0.f)
           + fminf(f4,0.f)+fminf(f5,0.f)+fminf(f6,0.f)+fminf(f7,0.f);

        if (!fast) {
            float* fp = &s_feat[side][i][0];
            fp[0]=f0; fp[1]=f1; fp[2]=f2; fp[3]=f3;
            fp[4]=f4; fp[5]=f5; fp[6]=f6; fp[7]=f7;
        }
    }

    if (fast) {
        // ---- per-warp store of its own 16 rows: no block barrier ----
        const int w    = tid >> 5;          // 0..7
        const int lane = tid & 31;
        const int sdw  = w >> 2;            // warp's side
        const int lb   = (w & 3) << 4;      // first l of this warp

        float4 vp = ((const float4*)s_Vp)[lane];
        float4 vn = ((const float4*)s_Vn)[lane];
        float4 bb = ((const float4*)s_Vb)[lane];

        float4* out4 = (float4*)out +
            (((size_t)sdw * B + b) * LQ + lb) * (DQ / 4);
        #pragma unroll
        for (int r = 0; r < 16; ++r) {
            float spr = __shfl_sync(0xFFFFFFFFu, sp, 2 * r);
            float snr = __shfl_sync(0xFFFFFFFFu, sn, 2 * r);
            float4 y;
            y.x = fmaf(spr, vp.x, fmaf(snr, vn.x, bb.x));
            y.y = fmaf(spr, vp.y, fmaf(snr, vn.y, bb.y));
            y.z = fmaf(spr, vp.z, fmaf(snr, vn.z, bb.z));
            y.w = fmaf(spr, vp.w, fmaf(snr, vn.w, bb.w));
            __stcs(&out4[r * 32 + lane], y);
        }
    } else {
        // ---- general-b1 path (never taken with this dataset's b1 == 0) ----
        __syncthreads();
        __shared__ float sW1[DQ], sb1[DQ];
        if (tid < DQ) { sW1[tid] = W1[tid]; sb1[tid] = b1[tid]; }
        __syncthreads();
        const size_t sideStride = (size_t)B * (LQ * DQ);
        for (int wdx = tid; wdx < 2 * LQ * DQ; wdx += 256) {
            int e    = wdx & 127;
            int row  = wdx >> 7;
            int sd   = row >> 6, l = row & 63;
            float y = 8.f * __ldg(&b2[e]);
            #pragma unroll
            for (int f = 0; f < 8; ++f) {
                float fv  = s_feat[sd][l][f];
                float acc = 0.f;
                for (int d = 0; d < DQ; ++d) {
                    float h = fmaxf(fmaf(fv, sW1[d], sb1[d]), 0.f);
                    acc = fmaf(h, __ldg(&W2[d * DQ + e]), acc);
                }
                y += acc;
            }
            out[(size_t)sd * sideStride + (size_t)b * (LQ * DQ) + (size_t)l * DQ + e] = y;
        }
    }
}

// ---------------------------------------------------------------------------
extern "C" void kernel_launch(void* const* d_in, const int* in_sizes, int n_in,
                              void* d_out, int out_size) {
    const int*   src_ids = (const int*)  d_in[0];
    const int*   dst_ids = (const int*)  d_in[1];
    const int*   src_nid = (const int*)  d_in[2];
    const int*   dst_nid = (const int*)  d_in[3];
    const float* itimes  = (const float*)d_in[4];
    const float* src_t   = (const float*)d_in[5];
    const float* dst_t   = (const float*)d_in[6];
    const float* W1      = (const float*)d_in[7];
    const float* b1      = (const float*)d_in[8];
    const float* W2      = (const float*)d_in[9];
    const float* b2      = (const float*)d_in[10];
    float* out = (float*)d_out;
    int B = in_sizes[2];  // src_node_ids count

    prep_kernel<<<4, 256>>>(W1, b1, W2, b2);
    lpe_main_kernel<<<B, 256>>>(src_ids, dst_ids, src_nid, dst_nid,
                                itimes, src_t, dst_t,
                                W1, b1, W2, b2, out, B);
}